// round 5
// baseline (speedup 1.0000x reference)
#include <cuda_runtime.h>
#include <math.h>

// Scratch: one full-size intermediate buffer (B*M*N floats = 134 MB).
#define SCRATCH_ELEMS (2ull * 4096ull * 4096ull)
__device__ float g_scratch[SCRATCH_ELEMS];

// Problem shape fixed: B=2, M=N=4096. Real-packed FFT length = 2048.
#define NN 4096
#define HH 2048

__device__ __forceinline__ float2 cadd(float2 a, float2 b){ return make_float2(a.x+b.x, a.y+b.y); }
__device__ __forceinline__ float2 csub(float2 a, float2 b){ return make_float2(a.x-b.x, a.y-b.y); }
__device__ __forceinline__ float2 cmul(float2 a, float2 b){
    return make_float2(fmaf(a.x, b.x, -a.y*b.y), fmaf(a.x, b.y, a.y*b.x));
}
__device__ __forceinline__ float2 mulip(float2 a){ return make_float2(-a.y, a.x); }  // * (+i)

// Pad one float2 every 16.
#define PIDX(a) ((a) + ((a) >> 4))
#define PBUF (HH + (HH >> 4))   // 2176 float2

// ---- 16-point inverse DFT in registers ----
__device__ __forceinline__ void r16_bfly(float2 g[16]) {
    const float C8 = 0.70710678118654752f;
    const float2 W1 = make_float2( 0.92387953251128674f,  0.38268343236508978f);
    const float2 W2 = make_float2( C8,  C8);
    const float2 W3 = make_float2( 0.38268343236508978f,  0.92387953251128674f);
    const float2 W6 = make_float2(-C8,  C8);
    const float2 W9 = make_float2(-0.92387953251128674f, -0.38268343236508978f);
    float2 c[16];
#pragma unroll
    for (int t0 = 0; t0 < 4; t0++) {
        float2 x0 = g[t0], x1 = g[t0+4], x2 = g[t0+8], x3 = g[t0+12];
        float2 s02 = cadd(x0,x2), d02 = csub(x0,x2);
        float2 s13 = cadd(x1,x3), d13 = csub(x1,x3);
        float2 id13 = mulip(d13);
        c[t0*4+0] = cadd(s02,s13);
        c[t0*4+1] = cadd(d02,id13);
        c[t0*4+2] = csub(s02,s13);
        c[t0*4+3] = csub(d02,id13);
    }
    c[5]  = cmul(c[5],  W1);
    c[6]  = cmul(c[6],  W2);
    c[7]  = cmul(c[7],  W3);
    c[9]  = cmul(c[9],  W2);
    c[10] = mulip(c[10]);
    c[11] = cmul(c[11], W6);
    c[13] = cmul(c[13], W3);
    c[14] = cmul(c[14], W6);
    c[15] = cmul(c[15], W9);
#pragma unroll
    for (int u0 = 0; u0 < 4; u0++) {
        float2 x0 = c[u0], x1 = c[4+u0], x2 = c[8+u0], x3 = c[12+u0];
        float2 s02 = cadd(x0,x2), d02 = csub(x0,x2);
        float2 s13 = cadd(x1,x3), d13 = csub(x1,x3);
        float2 id13 = mulip(d13);
        g[u0]    = cadd(s02,s13);
        g[u0+4]  = cadd(d02,id13);
        g[u0+8]  = csub(s02,s13);
        g[u0+12] = csub(d02,id13);
    }
}

// ---- 8-point inverse DFT in registers (a[u] -> B_u) ----
__device__ __forceinline__ void r8_bfly(float2 a[8]) {
    const float C8 = 0.70710678118654752f;
    float2 e0 = cadd(a[0],a[4]), e1 = cadd(a[1],a[5]);
    float2 e2 = cadd(a[2],a[6]), e3 = cadd(a[3],a[7]);
    float2 o0 = csub(a[0],a[4]), o1 = csub(a[1],a[5]);
    float2 o2 = csub(a[2],a[6]), o3 = csub(a[3],a[7]);
    o1 = make_float2(C8*(o1.x - o1.y),  C8*(o1.x + o1.y));
    o2 = mulip(o2);
    o3 = make_float2(-C8*(o3.x + o3.y), C8*(o3.x - o3.y));
    float2 t0 = cadd(e0,e2), t1 = csub(e0,e2);
    float2 t2 = cadd(e1,e3), t3 = csub(e1,e3);
    float2 it3 = mulip(t3);
    float2 u0 = cadd(o0,o2), u1 = csub(o0,o2);
    float2 u2 = cadd(o1,o3), u3 = csub(o1,o3);
    float2 iu3 = mulip(u3);
    a[0] = cadd(t0,t2);  a[4] = csub(t0,t2);
    a[2] = cadd(t1,it3); a[6] = csub(t1,it3);
    a[1] = cadd(u0,u2);  a[5] = csub(u0,u2);
    a[3] = cadd(u1,iu3); a[7] = csub(u1,iu3);
}

// ---------------------------------------------------------------------------
// Kernel 1 (rows): Makhoul pre-twiddle -> real-packed G (2048) -> radix
// 16/16/8 Stockham inverse FFT -> de-interleave epilogue. 128 thr, 1 row/CTA.
// MODE 0 = IDCT-II inverse, MODE 1 = IDXST.
// ---------------------------------------------------------------------------
template <int MODE>
__global__ __launch_bounds__(128, 4)
void dct_fft_kernel(const float* __restrict__ in,
                    const float2* __restrict__ expk,
                    float* __restrict__ out) {
    __shared__ __align__(16) float2 sX[PBUF];
    __shared__ __align__(16) float2 sY[PBUF];
    float* xs = (float*)sX;

    const int idx = threadIdx.x;
    const size_t base = (size_t)blockIdx.x * (size_t)NN;

    {
        const float4* in4 = (const float4*)(in + base);
        float4* xs4 = (float4*)xs;
#pragma unroll
        for (int i = idx; i < NN/4; i += 128) xs4[i] = in4[i];
    }
    __syncthreads();

    // Stage A: prologue + radix-16 + twiddle, write sY.
    {
        float2 g[16];
        const float2 E32 = make_float2(0.98078528040323044f, 0.19509032201612827f);
        float sn, cs;
        __sincosf((float)(2.0*M_PI/4096.0) * (float)idx, &sn, &cs);
        float2 w = make_float2(cs, sn);
#pragma unroll
        for (int t = 0; t < 16; t++) {
            const int j = idx + 128*t;
            float Xa0, Xb0, Xa1, Xb1;
            if (MODE == 0) {
                Xa0 = xs[j];
                Xb0 = (j == 0) ? 0.0f : xs[NN - j];
                Xa1 = xs[j + HH];
                Xb1 = xs[(j == 0) ? HH : (HH - j)];
            } else {
                Xa0 = (j == 0) ? 0.0f : xs[NN - j];
                Xb0 = (j == 0) ? 0.0f : xs[j];
                Xa1 = xs[(j == 0) ? HH : (HH - j)];
                Xb1 = xs[j + HH];
            }
            const float2 ea = expk[j];
            const float2 eb = expk[j + HH];
            float2 V0 = make_float2(0.5f*(Xa0*ea.x + Xb0*ea.y),
                                    0.5f*(Xa0*ea.y - Xb0*ea.x));
            float2 V1 = make_float2(0.5f*(Xa1*eb.x + Xb1*eb.y),
                                    0.5f*(Xa1*eb.y - Xb1*eb.x));
            float2 S = cadd(V0, V1);
            float2 D = csub(V0, V1);
            float2 wd = cmul(w, D);
            g[t] = make_float2(S.x - wd.y, S.y + wd.x);
            w = cmul(w, E32);
        }
        r16_bfly(g);
        __sincosf((float)(2.0*M_PI/2048.0) * (float)idx, &sn, &cs);
        const float2 w1 = make_float2(cs, sn);
        sY[PIDX(16*idx)] = g[0];
        float2 wu = w1;
#pragma unroll
        for (int u = 1; u < 16; u++) {
            sY[PIDX(16*idx + u)] = cmul(g[u], wu);
            wu = cmul(wu, w1);
        }
    }
    __syncthreads();

    // Stage B: radix-16, S=16.
    {
        float2 g[16];
#pragma unroll
        for (int t = 0; t < 16; t++) g[t] = sY[PIDX(idx + 128*t)];
        r16_bfly(g);
        const int p = idx >> 4, j = idx & 15;
        float sn, cs;
        __sincosf((float)(2.0*M_PI/128.0) * (float)p, &sn, &cs);
        const float2 w1 = make_float2(cs, sn);
        const int ob = j + 256*p;
        sX[PIDX(ob)] = g[0];
        float2 wu = w1;
#pragma unroll
        for (int u = 1; u < 16; u++) {
            sX[PIDX(ob + 16*u)] = cmul(g[u], wu);
            wu = cmul(wu, w1);
        }
    }
    __syncthreads();

    // Stage C: radix-8, S=256, fused with epilogue.
    {
        const int b1 = idx, b2 = 255 - idx;
        float2 A[8], Bv[8];
#pragma unroll
        for (int u = 0; u < 8; u++) A[u]  = sX[PIDX(b1 + 256*u)];
#pragma unroll
        for (int u = 0; u < 8; u++) Bv[u] = sX[PIDX(b2 + 256*u)];
        r8_bfly(A);
        r8_bfly(Bv);
        const float sgn = (MODE == 1) ? -1.0f : 1.0f;
        float4* out4 = (float4*)(out + base);
#pragma unroll
        for (int u = 0; u < 4; u++) {
            float2 z1 = A[u], z2 = Bv[7-u];
            out4[b1 + 256*u] = make_float4(z1.x, sgn*z2.y, z1.y, sgn*z2.x);
            z1 = Bv[u]; z2 = A[7-u];
            out4[b2 + 256*u] = make_float4(z1.x, sgn*z2.y, z1.y, sgn*z2.x);
        }
    }
}

// ---------------------------------------------------------------------------
// Kernel 2 (columns): IDCT along M directly on (B, M, N) layout. 4 columns
// per CTA, 512 threads (128/column), single shared buffer per column,
// radix 8/8/8/4 Stockham, fused prologue and epilogue. No transposes.
// ---------------------------------------------------------------------------
#define CSTRIDE_F 4360

template <int S>
__device__ __forceinline__ void r8_stage_ip(float2* zb, int t) {
    float2 A[2][8];
#pragma unroll
    for (int h = 0; h < 2; h++) {
        const int idx = t + 128*h;
#pragma unroll
        for (int u = 0; u < 8; u++) A[h][u] = zb[PIDX(idx + 256*u)];
    }
    __syncthreads();
#pragma unroll
    for (int h = 0; h < 2; h++) {
        const int idx = t + 128*h;
        r8_bfly(A[h]);
        const int p = idx / S, j = idx - p*S;
        float sn, cs;
        __sincosf((float)(2.0*M_PI*(double)S/2048.0) * (float)p, &sn, &cs);
        const float2 w1 = make_float2(cs, sn);
        const int ob = j + 8*S*p;
        zb[PIDX(ob)] = A[h][0];
        float2 wu = w1;
#pragma unroll
        for (int u = 1; u < 8; u++) {
            zb[PIDX(ob + u*S)] = cmul(A[h][u], wu);
            wu = cmul(wu, w1);
        }
    }
    __syncthreads();
}

__global__ __launch_bounds__(512, 2)
void idct_col_kernel(const float* __restrict__ in,
                     const float2* __restrict__ expk,
                     float* __restrict__ out) {
    extern __shared__ __align__(16) float smf[];
    const int tid = threadIdx.x;
    const int b  = blockIdx.x >> 10;          // N/4 = 1024 CTAs per batch
    const int c0 = (blockIdx.x & 1023) << 2;
    const size_t base = (size_t)b * (size_t)NN * (size_t)NN + (size_t)c0;

    // ---- load 4 columns ----
    {
        const int cc = tid & 3;
        const int r0 = tid >> 2;               // 0..127
        float* xs = smf + cc * CSTRIDE_F;
        const float* inp = in + base + cc;
#pragma unroll
        for (int k = 0; k < 32; k++) {
            const int r = r0 + 128*k;
            xs[r] = inp[(size_t)r * NN];
        }
    }
    __syncthreads();

    const int t = tid & 127;
    const int c = tid >> 7;
    float* xs = smf + c * CSTRIDE_F;
    float2* zb = (float2*)xs;

    // ---- prologue: G[j], j = t + 128k, entirely in registers (IDCT form) ----
    float2 G[16];
    {
        // step per k: e^{2pi i * 128/4096} = e^{2pi i/32}  (FIXED constant)
        const float2 STEP = make_float2(0.98078528040323044f, 0.19509032201612827f);
        float sn, cs;
        __sincosf((float)(2.0*M_PI/4096.0) * (float)t, &sn, &cs);
        float2 w = make_float2(cs, sn);
#pragma unroll
        for (int k = 0; k < 16; k++) {
            const int j = t + 128*k;
            const float Xa0 = xs[j];
            const float Xb0 = (j == 0) ? 0.0f : xs[NN - j];
            const float Xa1 = xs[j + HH];
            const float Xb1 = xs[(j == 0) ? HH : (HH - j)];
            const float2 ea = expk[j];
            const float2 eb = expk[j + HH];
            float2 V0 = make_float2(0.5f*(Xa0*ea.x + Xb0*ea.y),
                                    0.5f*(Xa0*ea.y - Xb0*ea.x));
            float2 V1 = make_float2(0.5f*(Xa1*eb.x + Xb1*eb.y),
                                    0.5f*(Xa1*eb.y - Xb1*eb.x));
            float2 S = cadd(V0, V1);
            float2 D = csub(V0, V1);
            float2 wd = cmul(w, D);
            G[k] = make_float2(S.x - wd.y, S.y + wd.x);
            w = cmul(w, STEP);
        }
    }
    __syncthreads();   // all xs reads done before stage-1 writes

    // ---- stage 1: radix-8, S=1, inputs straight from G registers ----
#pragma unroll
    for (int h = 0; h < 2; h++) {
        float2 a[8];
#pragma unroll
        for (int u = 0; u < 8; u++) a[u] = G[h + 2*u];   // G[idx + 256u]
        r8_bfly(a);
        const int idx = t + 128*h;
        float sn, cs;
        __sincosf((float)(2.0*M_PI/2048.0) * (float)idx, &sn, &cs);
        const float2 w1 = make_float2(cs, sn);
        zb[PIDX(8*idx)] = a[0];
        float2 wu = w1;
#pragma unroll
        for (int u = 1; u < 8; u++) {
            zb[PIDX(8*idx + u)] = cmul(a[u], wu);
            wu = cmul(wu, w1);
        }
    }
    __syncthreads();

    // ---- stages 2 and 3 ----
    r8_stage_ip<8>(zb, t);
    r8_stage_ip<64>(zb, t);

    // ---- stage 4: radix-4, S=512, slots private per thread (no barrier) ----
#pragma unroll
    for (int h = 0; h < 4; h++) {
        const int idx = t + 128*h;
        float2 a0 = zb[PIDX(idx)],        a1 = zb[PIDX(idx + 512)];
        float2 a2 = zb[PIDX(idx + 1024)], a3 = zb[PIDX(idx + 1536)];
        float2 t0 = cadd(a0,a2), t1 = csub(a0,a2);
        float2 t2 = cadd(a1,a3), t3 = csub(a1,a3);
        float2 it3 = mulip(t3);
        zb[PIDX(idx)]        = cadd(t0,t2);
        zb[PIDX(idx + 512)]  = cadd(t1,it3);
        zb[PIDX(idx + 1024)] = csub(t0,t2);
        zb[PIDX(idx + 1536)] = csub(t1,it3);
    }
    __syncthreads();

    // ---- store with fused de-interleave epilogue (IDCT: no sign flip) ----
    {
        const int cc = tid & 3;
        const int r0 = tid >> 2;
        const float2* zc = (const float2*)(smf + cc * CSTRIDE_F);
        float* op = out + base + cc;
#pragma unroll
        for (int k = 0; k < 32; k++) {
            const int r = r0 + 128*k;
            const int vidx = (r & 1) ? (4095 - (r >> 1)) : (r >> 1);
            const float2 z = zc[PIDX(vidx >> 1)];
            op[(size_t)r * NN] = (vidx & 1) ? z.y : z.x;
        }
    }
}

extern "C" void kernel_launch(void* const* d_in, const int* in_sizes, int n_in,
                              void* d_out, int out_size) {
    const float*  x     = (const float*)d_in[0];
    const float2* expkM = (const float2*)d_in[1];
    const float2* expkN = (const float2*)d_in[2];
    const int M = in_sizes[1] / 2;            // 4096
    const int N = in_sizes[2] / 2;            // 4096
    const int B = in_sizes[0] / (M * N);      // 2
    float* out = (float*)d_out;

    float* scratch = nullptr;
    cudaGetSymbolAddress((void**)&scratch, g_scratch);

    const int smem2 = 4 * CSTRIDE_F * 4;      // 69760 B
    cudaFuncSetAttribute(idct_col_kernel,
                         cudaFuncAttributeMaxDynamicSharedMemorySize, smem2);

    // Pass 1: IDXST along N (contiguous rows).  x -> scratch   (B, M, N)
    dct_fft_kernel<1><<<B * M, 128>>>(x, expkN, scratch);

    // Pass 2: IDCT along M (columns, no transpose).  scratch -> d_out
    idct_col_kernel<<<B * (N / 4), 512, smem2>>>(scratch, expkM, out);
}

// round 6
// speedup vs baseline: 1.1457x; 1.1457x over previous
#include <cuda_runtime.h>
#include <math.h>

// Scratch: one full-size intermediate buffer (B*M*N floats = 134 MB).
#define SCRATCH_ELEMS (2ull * 4096ull * 4096ull)
__device__ float g_scratch[SCRATCH_ELEMS];

// Problem shape fixed: B=2, M=N=4096. Real-packed FFT length = 2048.
#define NN 4096
#define HH 2048

__device__ __forceinline__ float2 cadd(float2 a, float2 b){ return make_float2(a.x+b.x, a.y+b.y); }
__device__ __forceinline__ float2 csub(float2 a, float2 b){ return make_float2(a.x-b.x, a.y-b.y); }
__device__ __forceinline__ float2 cmul(float2 a, float2 b){
    return make_float2(fmaf(a.x, b.x, -a.y*b.y), fmaf(a.x, b.y, a.y*b.x));
}
__device__ __forceinline__ float2 mulip(float2 a){ return make_float2(-a.y, a.x); }  // * (+i)

// Pad one float2 every 16.
#define PIDX(a) ((a) + ((a) >> 4))
#define PBUF (HH + (HH >> 4))   // 2176 float2

// ---- 16-point inverse DFT in registers ----
__device__ __forceinline__ void r16_bfly(float2 g[16]) {
    const float C8 = 0.70710678118654752f;
    const float2 W1 = make_float2( 0.92387953251128674f,  0.38268343236508978f);
    const float2 W2 = make_float2( C8,  C8);
    const float2 W3 = make_float2( 0.38268343236508978f,  0.92387953251128674f);
    const float2 W6 = make_float2(-C8,  C8);
    const float2 W9 = make_float2(-0.92387953251128674f, -0.38268343236508978f);
    float2 c[16];
#pragma unroll
    for (int t0 = 0; t0 < 4; t0++) {
        float2 x0 = g[t0], x1 = g[t0+4], x2 = g[t0+8], x3 = g[t0+12];
        float2 s02 = cadd(x0,x2), d02 = csub(x0,x2);
        float2 s13 = cadd(x1,x3), d13 = csub(x1,x3);
        float2 id13 = mulip(d13);
        c[t0*4+0] = cadd(s02,s13);
        c[t0*4+1] = cadd(d02,id13);
        c[t0*4+2] = csub(s02,s13);
        c[t0*4+3] = csub(d02,id13);
    }
    c[5]  = cmul(c[5],  W1);
    c[6]  = cmul(c[6],  W2);
    c[7]  = cmul(c[7],  W3);
    c[9]  = cmul(c[9],  W2);
    c[10] = mulip(c[10]);
    c[11] = cmul(c[11], W6);
    c[13] = cmul(c[13], W3);
    c[14] = cmul(c[14], W6);
    c[15] = cmul(c[15], W9);
#pragma unroll
    for (int u0 = 0; u0 < 4; u0++) {
        float2 x0 = c[u0], x1 = c[4+u0], x2 = c[8+u0], x3 = c[12+u0];
        float2 s02 = cadd(x0,x2), d02 = csub(x0,x2);
        float2 s13 = cadd(x1,x3), d13 = csub(x1,x3);
        float2 id13 = mulip(d13);
        g[u0]    = cadd(s02,s13);
        g[u0+4]  = cadd(d02,id13);
        g[u0+8]  = csub(s02,s13);
        g[u0+12] = csub(d02,id13);
    }
}

// ---- 8-point inverse DFT in registers (a[u] -> B_u) ----
__device__ __forceinline__ void r8_bfly(float2 a[8]) {
    const float C8 = 0.70710678118654752f;
    float2 e0 = cadd(a[0],a[4]), e1 = cadd(a[1],a[5]);
    float2 e2 = cadd(a[2],a[6]), e3 = cadd(a[3],a[7]);
    float2 o0 = csub(a[0],a[4]), o1 = csub(a[1],a[5]);
    float2 o2 = csub(a[2],a[6]), o3 = csub(a[3],a[7]);
    o1 = make_float2(C8*(o1.x - o1.y),  C8*(o1.x + o1.y));
    o2 = mulip(o2);
    o3 = make_float2(-C8*(o3.x + o3.y), C8*(o3.x - o3.y));
    float2 t0 = cadd(e0,e2), t1 = csub(e0,e2);
    float2 t2 = cadd(e1,e3), t3 = csub(e1,e3);
    float2 it3 = mulip(t3);
    float2 u0 = cadd(o0,o2), u1 = csub(o0,o2);
    float2 u2 = cadd(o1,o3), u3 = csub(o1,o3);
    float2 iu3 = mulip(u3);
    a[0] = cadd(t0,t2);  a[4] = csub(t0,t2);
    a[2] = cadd(t1,it3); a[6] = csub(t1,it3);
    a[1] = cadd(u0,u2);  a[5] = csub(u0,u2);
    a[3] = cadd(u1,iu3); a[7] = csub(u1,iu3);
}

// ---------------------------------------------------------------------------
// Kernel 1 (rows): Makhoul pre-twiddle -> real-packed G (2048) -> radix
// 16/16/8 Stockham inverse FFT -> de-interleave epilogue. 128 thr, 1 row/CTA.
// MODE 0 = IDCT-II inverse, MODE 1 = IDXST.
// ---------------------------------------------------------------------------
template <int MODE>
__global__ __launch_bounds__(128, 4)
void dct_fft_kernel(const float* __restrict__ in,
                    const float2* __restrict__ expk,
                    float* __restrict__ out) {
    __shared__ __align__(16) float2 sX[PBUF];
    __shared__ __align__(16) float2 sY[PBUF];
    float* xs = (float*)sX;

    const int idx = threadIdx.x;
    const size_t base = (size_t)blockIdx.x * (size_t)NN;

    {
        const float4* in4 = (const float4*)(in + base);
        float4* xs4 = (float4*)xs;
#pragma unroll
        for (int i = idx; i < NN/4; i += 128) xs4[i] = in4[i];
    }
    __syncthreads();

    // Stage A: prologue + radix-16 + twiddle, write sY.
    {
        float2 g[16];
        const float2 E32 = make_float2(0.98078528040323044f, 0.19509032201612827f);
        float sn, cs;
        __sincosf((float)(2.0*M_PI/4096.0) * (float)idx, &sn, &cs);
        float2 w = make_float2(cs, sn);
#pragma unroll
        for (int t = 0; t < 16; t++) {
            const int j = idx + 128*t;
            float Xa0, Xb0, Xa1, Xb1;
            if (MODE == 0) {
                Xa0 = xs[j];
                Xb0 = (j == 0) ? 0.0f : xs[NN - j];
                Xa1 = xs[j + HH];
                Xb1 = xs[(j == 0) ? HH : (HH - j)];
            } else {
                Xa0 = (j == 0) ? 0.0f : xs[NN - j];
                Xb0 = (j == 0) ? 0.0f : xs[j];
                Xa1 = xs[(j == 0) ? HH : (HH - j)];
                Xb1 = xs[j + HH];
            }
            const float2 ea = expk[j];
            const float2 eb = expk[j + HH];
            float2 V0 = make_float2(0.5f*(Xa0*ea.x + Xb0*ea.y),
                                    0.5f*(Xa0*ea.y - Xb0*ea.x));
            float2 V1 = make_float2(0.5f*(Xa1*eb.x + Xb1*eb.y),
                                    0.5f*(Xa1*eb.y - Xb1*eb.x));
            float2 S = cadd(V0, V1);
            float2 D = csub(V0, V1);
            float2 wd = cmul(w, D);
            g[t] = make_float2(S.x - wd.y, S.y + wd.x);
            w = cmul(w, E32);
        }
        r16_bfly(g);
        __sincosf((float)(2.0*M_PI/2048.0) * (float)idx, &sn, &cs);
        const float2 w1 = make_float2(cs, sn);
        sY[PIDX(16*idx)] = g[0];
        float2 wu = w1;
#pragma unroll
        for (int u = 1; u < 16; u++) {
            sY[PIDX(16*idx + u)] = cmul(g[u], wu);
            wu = cmul(wu, w1);
        }
    }
    __syncthreads();

    // Stage B: radix-16, S=16.
    {
        float2 g[16];
#pragma unroll
        for (int t = 0; t < 16; t++) g[t] = sY[PIDX(idx + 128*t)];
        r16_bfly(g);
        const int p = idx >> 4, j = idx & 15;
        float sn, cs;
        __sincosf((float)(2.0*M_PI/128.0) * (float)p, &sn, &cs);
        const float2 w1 = make_float2(cs, sn);
        const int ob = j + 256*p;
        sX[PIDX(ob)] = g[0];
        float2 wu = w1;
#pragma unroll
        for (int u = 1; u < 16; u++) {
            sX[PIDX(ob + 16*u)] = cmul(g[u], wu);
            wu = cmul(wu, w1);
        }
    }
    __syncthreads();

    // Stage C: radix-8, S=256, fused with epilogue.
    {
        const int b1 = idx, b2 = 255 - idx;
        float2 A[8], Bv[8];
#pragma unroll
        for (int u = 0; u < 8; u++) A[u]  = sX[PIDX(b1 + 256*u)];
#pragma unroll
        for (int u = 0; u < 8; u++) Bv[u] = sX[PIDX(b2 + 256*u)];
        r8_bfly(A);
        r8_bfly(Bv);
        const float sgn = (MODE == 1) ? -1.0f : 1.0f;
        float4* out4 = (float4*)(out + base);
#pragma unroll
        for (int u = 0; u < 4; u++) {
            float2 z1 = A[u], z2 = Bv[7-u];
            out4[b1 + 256*u] = make_float4(z1.x, sgn*z2.y, z1.y, sgn*z2.x);
            z1 = Bv[u]; z2 = A[7-u];
            out4[b2 + 256*u] = make_float4(z1.x, sgn*z2.y, z1.y, sgn*z2.x);
        }
    }
}

// ---------------------------------------------------------------------------
// Kernel 2 (columns): IDCT along M directly on (B, M, N) layout.
// 8 columns per CTA, 1024 threads (128/column), single in-place shared
// buffer per column, radix 8/8/8/4 Stockham, fused prologue/epilogue.
// 32B global granule on both load and store.
// CSTRIDE_F = 4356 floats (>= 4350 needed; ==4 mod 32 for bank hygiene).
// ---------------------------------------------------------------------------
#define CSTRIDE_F 4356
#define NCOLS 8

template <int S>
__device__ __forceinline__ void r8_stage_ip(float2* zb, int t) {
    float2 A[2][8];
#pragma unroll
    for (int h = 0; h < 2; h++) {
        const int idx = t + 128*h;
#pragma unroll
        for (int u = 0; u < 8; u++) A[h][u] = zb[PIDX(idx + 256*u)];
    }
    __syncthreads();
#pragma unroll
    for (int h = 0; h < 2; h++) {
        const int idx = t + 128*h;
        r8_bfly(A[h]);
        const int p = idx / S, j = idx - p*S;
        float sn, cs;
        __sincosf((float)(2.0*M_PI*(double)S/2048.0) * (float)p, &sn, &cs);
        const float2 w1 = make_float2(cs, sn);
        const int ob = j + 8*S*p;
        zb[PIDX(ob)] = A[h][0];
        float2 wu = w1;
#pragma unroll
        for (int u = 1; u < 8; u++) {
            zb[PIDX(ob + u*S)] = cmul(A[h][u], wu);
            wu = cmul(wu, w1);
        }
    }
    __syncthreads();
}

__global__ __launch_bounds__(1024, 1)
void idct_col_kernel(const float* __restrict__ in,
                     const float2* __restrict__ expk,
                     float* __restrict__ out) {
    extern __shared__ __align__(16) float smf[];
    const int tid = threadIdx.x;
    const int b  = blockIdx.x >> 9;           // N/8 = 512 CTAs per batch
    const int c0 = (blockIdx.x & 511) << 3;
    const size_t base = (size_t)b * (size_t)NN * (size_t)NN + (size_t)c0;

    // ---- load 8 columns (float2 => 32B per warp-row-chunk) ----
    {
        const int cc = tid & 3;                // float2 column-pair 0..3
        const int r0 = tid >> 2;               // 0..255
        const float2* inp2 = (const float2*)(in + base);
        float* xsA = smf + (2*cc)     * CSTRIDE_F;
        float* xsB = smf + (2*cc + 1) * CSTRIDE_F;
#pragma unroll
        for (int k = 0; k < 16; k++) {
            const int r = r0 + 256*k;
            const float2 v = inp2[(size_t)r * (NN/2) + cc];
            xsA[r] = v.x;
            xsB[r] = v.y;
        }
    }
    __syncthreads();

    const int t = tid & 127;
    const int c = tid >> 7;                    // 0..7
    float* xs = smf + c * CSTRIDE_F;
    float2* zb = (float2*)xs;

    // ---- prologue: G[j], j = t + 128k, entirely in registers (IDCT form) ----
    float2 G[16];
    {
        // step per k: e^{2pi i * 128/4096} = e^{2pi i/32}
        const float2 STEP = make_float2(0.98078528040323044f, 0.19509032201612827f);
        float sn, cs;
        __sincosf((float)(2.0*M_PI/4096.0) * (float)t, &sn, &cs);
        float2 w = make_float2(cs, sn);
#pragma unroll
        for (int k = 0; k < 16; k++) {
            const int j = t + 128*k;
            const float Xa0 = xs[j];
            const float Xb0 = (j == 0) ? 0.0f : xs[NN - j];
            const float Xa1 = xs[j + HH];
            const float Xb1 = xs[(j == 0) ? HH : (HH - j)];
            const float2 ea = expk[j];
            const float2 eb = expk[j + HH];
            float2 V0 = make_float2(0.5f*(Xa0*ea.x + Xb0*ea.y),
                                    0.5f*(Xa0*ea.y - Xb0*ea.x));
            float2 V1 = make_float2(0.5f*(Xa1*eb.x + Xb1*eb.y),
                                    0.5f*(Xa1*eb.y - Xb1*eb.x));
            float2 S = cadd(V0, V1);
            float2 D = csub(V0, V1);
            float2 wd = cmul(w, D);
            G[k] = make_float2(S.x - wd.y, S.y + wd.x);
            w = cmul(w, STEP);
        }
    }
    __syncthreads();   // all xs reads done before stage-1 writes

    // ---- stage 1: radix-8, S=1, inputs straight from G registers ----
#pragma unroll
    for (int h = 0; h < 2; h++) {
        float2 a[8];
#pragma unroll
        for (int u = 0; u < 8; u++) a[u] = G[h + 2*u];   // G[idx + 256u]
        r8_bfly(a);
        const int idx = t + 128*h;
        float sn, cs;
        __sincosf((float)(2.0*M_PI/2048.0) * (float)idx, &sn, &cs);
        const float2 w1 = make_float2(cs, sn);
        zb[PIDX(8*idx)] = a[0];
        float2 wu = w1;
#pragma unroll
        for (int u = 1; u < 8; u++) {
            zb[PIDX(8*idx + u)] = cmul(a[u], wu);
            wu = cmul(wu, w1);
        }
    }
    __syncthreads();

    // ---- stages 2 and 3 ----
    r8_stage_ip<8>(zb, t);
    r8_stage_ip<64>(zb, t);

    // ---- stage 4: radix-4, S=512, slots private per thread (no barrier) ----
#pragma unroll
    for (int h = 0; h < 4; h++) {
        const int idx = t + 128*h;
        float2 a0 = zb[PIDX(idx)],        a1 = zb[PIDX(idx + 512)];
        float2 a2 = zb[PIDX(idx + 1024)], a3 = zb[PIDX(idx + 1536)];
        float2 t0 = cadd(a0,a2), t1 = csub(a0,a2);
        float2 t2 = cadd(a1,a3), t3 = csub(a1,a3);
        float2 it3 = mulip(t3);
        zb[PIDX(idx)]        = cadd(t0,t2);
        zb[PIDX(idx + 512)]  = cadd(t1,it3);
        zb[PIDX(idx + 1024)] = csub(t0,t2);
        zb[PIDX(idx + 1536)] = csub(t1,it3);
    }
    __syncthreads();

    // ---- store with fused de-interleave epilogue (32B granule) ----
    {
        const int cc = tid & 7;
        const int r0 = tid >> 3;               // 0..127
        const float2* zc = (const float2*)(smf + cc * CSTRIDE_F);
        float* op = out + base + cc;
#pragma unroll
        for (int k = 0; k < 32; k++) {
            const int r = r0 + 128*k;
            const int vidx = (r & 1) ? (4095 - (r >> 1)) : (r >> 1);
            const float2 z = zc[PIDX(vidx >> 1)];
            op[(size_t)r * NN] = (vidx & 1) ? z.y : z.x;
        }
    }
}

extern "C" void kernel_launch(void* const* d_in, const int* in_sizes, int n_in,
                              void* d_out, int out_size) {
    const float*  x     = (const float*)d_in[0];
    const float2* expkM = (const float2*)d_in[1];
    const float2* expkN = (const float2*)d_in[2];
    const int M = in_sizes[1] / 2;            // 4096
    const int N = in_sizes[2] / 2;            // 4096
    const int B = in_sizes[0] / (M * N);      // 2
    float* out = (float*)d_out;

    float* scratch = nullptr;
    cudaGetSymbolAddress((void**)&scratch, g_scratch);

    const int smem2 = NCOLS * CSTRIDE_F * 4;  // 139392 B
    cudaFuncSetAttribute(idct_col_kernel,
                         cudaFuncAttributeMaxDynamicSharedMemorySize, smem2);

    // Pass 1: IDXST along N (contiguous rows).  x -> scratch   (B, M, N)
    dct_fft_kernel<1><<<B * M, 128>>>(x, expkN, scratch);

    // Pass 2: IDCT along M (columns, no transpose).  scratch -> d_out
    idct_col_kernel<<<B * (N / NCOLS), 1024, smem2>>>(scratch, expkM, out);
}